// round 15
// baseline (speedup 1.0000x reference)
#include <cuda_runtime.h>
#include <cuda_fp16.h>
#include <math.h>
#include <stdint.h>

// ---------------------------------------------------------------------------
// Problem constants
// ---------------------------------------------------------------------------
#define QL 2048
#define BSZ 2
#define DM 1024
#define NH 16
#define DH 64
#define DI 4096
#define NTOK (QL*BSZ)

// ---------------------------------------------------------------------------
// Scratch (device globals; no allocation allowed)
// ---------------------------------------------------------------------------
__device__ float g_heads[NTOK * 3 * DM];
__device__ float g_rk[QL * DM];
__device__ float g_attnvec[NTOK * DM];
__device__ float g_attnout[NTOK * DM];
__device__ float g_x[NTOK * DM];
__device__ float g_h[NTOK * DI];
__device__ float g_core[NTOK * DM];

// ---------------------------------------------------------------------------
// helpers
// ---------------------------------------------------------------------------
__device__ __forceinline__ float to_tf32(float v) {
    uint32_t u;
    asm("cvt.rna.tf32.f32 %0, %1;" : "=r"(u) : "f"(v));
    return __uint_as_float(u);
}

#define MMA_TF32(d, a, b)                                                      \
    asm volatile(                                                              \
        "mma.sync.aligned.m16n8k8.row.col.f32.tf32.tf32.f32 "                  \
        "{%0,%1,%2,%3},{%4,%5,%6,%7},{%8,%9},{%0,%1,%2,%3};\n"                 \
        : "+f"(d[0]), "+f"(d[1]), "+f"(d[2]), "+f"(d[3])                       \
        : "r"(a[0]), "r"(a[1]), "r"(a[2]), "r"(a[3]), "r"(b[0]), "r"(b[1]))

#define MMA_F16(d, a, b)                                                       \
    asm volatile(                                                              \
        "mma.sync.aligned.m16n8k16.row.col.f32.f16.f16.f32 "                   \
        "{%0,%1,%2,%3},{%4,%5,%6,%7},{%8,%9},{%0,%1,%2,%3};\n"                 \
        : "+f"(d[0]), "+f"(d[1]), "+f"(d[2]), "+f"(d[3])                       \
        : "r"(a[0]), "r"(a[1]), "r"(a[2]), "r"(a[3]), "r"(b[0]), "r"(b[1]))

__device__ __forceinline__ uint32_t h2u(__half2 h) { return *(uint32_t*)&h; }

// ---------------------------------------------------------------------------
// Pad kernel: ncu capture slot = launch index 3 (confirmed R12-R14).
// ---------------------------------------------------------------------------
__global__ void nop_kernel() {}

// ---------------------------------------------------------------------------
// Generic tf32 GEMM (unchanged, known-good)
// ---------------------------------------------------------------------------
template <int EPI>
__global__ void __launch_bounds__(256)
gemm_tf32(const float* __restrict__ A, const float* __restrict__ B,
          float* __restrict__ C, const float* __restrict__ bias,
          int M, int N, int K)
{
    const int bm = blockIdx.y * 128;
    const int bn = blockIdx.x * 128;

    __shared__ float As[128 * 36];
    __shared__ float Bs[32 * 136];

    const int tid = threadIdx.x;
    const int w   = tid >> 5;
    const int l   = tid & 31;
    const int g   = l >> 2;
    const int t   = l & 3;
    const int wm  = (w & 1) * 64;
    const int wn  = (w >> 1) * 32;

    float c[4][4][4];
    #pragma unroll
    for (int mt = 0; mt < 4; mt++)
        #pragma unroll
        for (int nt = 0; nt < 4; nt++)
            #pragma unroll
            for (int q = 0; q < 4; q++) c[mt][nt][q] = 0.f;

    float4 ra[4], rb[4];
    const int KT = K / 32;

    #define LOAD_G(kt)                                                         \
        {                                                                      \
            const float* Ap = A + (long)bm * K + (kt) * 32;                    \
            _Pragma("unroll")                                                  \
            for (int it = 0; it < 4; it++) {                                   \
                int f = tid + it * 256;                                        \
                int rr = f >> 3, c4 = f & 7;                                   \
                ra[it] = *(const float4*)(Ap + (long)rr * K + c4 * 4);         \
            }                                                                  \
            const float* Bp = B + (long)(kt) * 32 * N + bn;                    \
            _Pragma("unroll")                                                  \
            for (int it = 0; it < 4; it++) {                                   \
                int f = tid + it * 256;                                        \
                int rr = f >> 5, c4 = f & 31;                                  \
                rb[it] = *(const float4*)(Bp + (long)rr * N + c4 * 4);         \
            }                                                                  \
        }

    #define STORE_S()                                                          \
        {                                                                      \
            _Pragma("unroll")                                                  \
            for (int it = 0; it < 4; it++) {                                   \
                int f = tid + it * 256;                                        \
                int rr = f >> 3, c4 = f & 7;                                   \
                float* p = As + rr * 36 + c4 * 4;                              \
                p[0] = to_tf32(ra[it].x); p[1] = to_tf32(ra[it].y);            \
                p[2] = to_tf32(ra[it].z); p[3] = to_tf32(ra[it].w);            \
            }                                                                  \
            _Pragma("unroll")                                                  \
            for (int it = 0; it < 4; it++) {                                   \
                int f = tid + it * 256;                                        \
                int rr = f >> 5, c4 = f & 31;                                  \
                float* p = Bs + rr * 136 + c4 * 4;                             \
                p[0] = to_tf32(rb[it].x); p[1] = to_tf32(rb[it].y);            \
                p[2] = to_tf32(rb[it].z); p[3] = to_tf32(rb[it].w);            \
            }                                                                  \
        }

    LOAD_G(0);
    STORE_S();
    __syncthreads();

    for (int kt = 0; kt < KT; kt++) {
        if (kt + 1 < KT) LOAD_G(kt + 1);

        #pragma unroll
        for (int ks = 0; ks < 4; ks++) {
            uint32_t af[4][4], bf[4][2];
            #pragma unroll
            for (int mt = 0; mt < 4; mt++) {
                const float* ap = As + (wm + mt * 16) * 36 + ks * 8;
                af[mt][0] = __float_as_uint(ap[g * 36 + t]);
                af[mt][1] = __float_as_uint(ap[(g + 8) * 36 + t]);
                af[mt][2] = __float_as_uint(ap[g * 36 + t + 4]);
                af[mt][3] = __float_as_uint(ap[(g + 8) * 36 + t + 4]);
            }
            #pragma unroll
            for (int nt = 0; nt < 4; nt++) {
                const float* bp = Bs + (ks * 8) * 136 + wn + nt * 8;
                bf[nt][0] = __float_as_uint(bp[t * 136 + g]);
                bf[nt][1] = __float_as_uint(bp[(t + 4) * 136 + g]);
            }
            #pragma unroll
            for (int mt = 0; mt < 4; mt++)
                #pragma unroll
                for (int nt = 0; nt < 4; nt++)
                    MMA_TF32(c[mt][nt], af[mt], bf[nt]);
        }

        __syncthreads();
        if (kt + 1 < KT) {
            STORE_S();
            __syncthreads();
        }
    }

    #pragma unroll
    for (int mt = 0; mt < 4; mt++) {
        #pragma unroll
        for (int nt = 0; nt < 4; nt++) {
            int row0 = bm + wm + mt * 16 + g;
            int col  = bn + wn + nt * 8 + 2 * t;
            float v0 = c[mt][nt][0], v1 = c[mt][nt][1];
            float v2 = c[mt][nt][2], v3 = c[mt][nt][3];
            if (EPI == 1) {
                float b0 = bias[col], b1 = bias[col + 1];
                v0 = fmaxf(v0 + b0, 0.f); v1 = fmaxf(v1 + b1, 0.f);
                v2 = fmaxf(v2 + b0, 0.f); v3 = fmaxf(v3 + b1, 0.f);
            }
            float2 p01 = make_float2(v0, v1);
            float2 p23 = make_float2(v2, v3);
            *(float2*)(C + (long)row0 * N + col)       = p01;
            *(float2*)(C + (long)(row0 + 8) * N + col) = p23;
        }
    }
    #undef LOAD_G
    #undef STORE_S
}

// ---------------------------------------------------------------------------
// MMA flash causal rel-attention, v7: fp16 operands (f32 accumulate).
// R14 ncu: L1tex 55% = LDS-byte bound. fp16 mantissa (11b) == tf32 mantissa,
// so halving operand bytes keeps accuracy while halving the bound traffic:
//  - Q/K/relpos/P/V tiles stored as __half (stride 72 halves, conflict-free)
//  - mma.m16n8k16.f16 with f32 accum: half the HMMAs, half the frag loads
//  - V stored TRANSPOSED Vt[d][tj] so PV B-frags are contiguous half2
//  - S and BD buffers stay f32 (softmax stats precision); shift-at-store BD
//    and 4-lane-per-row softmax unchanged from R14 (proven).
// ---------------------------------------------------------------------------
#define H_STR 72       // half stride: 36 banks -> frag banks (4g+t)%32
#define F_STR 68       // f32 stride for S/BD

// smem byte offsets
#define QSH_OFF   0                       // 64*72 half = 9216
#define KSH_OFF   9216                    // 9216
#define RVH_OFF   18432                   // Rs (mma phase) then Vt (PV)
#define PH_OFF    27648                   // P half
#define SP_OFF    36864                   // S f32 64*68*4 = 17408
#define B0_OFF    54272                   // BD f32
#define B1_OFF    71680                   // BD f32
#define BRH_OFF   89088                   // 64 half = 128
#define CORR_OFF  89216                   // 64 f32
#define LINV_OFF  89472                   // 64 f32
#define SMEM_ATT  89728

__global__ void __launch_bounds__(256, 2)
attn_mma_kernel(const float* __restrict__ rwb, const float* __restrict__ rrb)
{
    extern __shared__ char smb[];
    __half* Qsh = (__half*)(smb + QSH_OFF);
    __half* Ksh = (__half*)(smb + KSH_OFF);
    __half* RVh = (__half*)(smb + RVH_OFF);
    __half* Ph  = (__half*)(smb + PH_OFF);
    float*  SP  = (float*)(smb + SP_OFF);
    float*  B0  = (float*)(smb + B0_OFF);
    float*  B1  = (float*)(smb + B1_OFF);
    __half* brh = (__half*)(smb + BRH_OFF);
    float*  corr_s = (float*)(smb + CORR_OFF);
    float*  linv_s = (float*)(smb + LINV_OFF);

    const int qt = 31 - (int)blockIdx.x;
    const int n  = blockIdx.y;
    const int b  = blockIdx.z;
    const int i0 = qt * 64;
    const int tid = threadIdx.x;
    const int w = tid >> 5, l = tid & 31;
    const int g = l >> 2, t = l & 3;
    const int roff = (w >> 1) * 16;
    const int coff = (w & 1) * 32;
    const float scale = 0.125f;

    // ---- prologue: delta bias (half) + QW tile (half) ----
    if (tid < 32) {
        float d0 = rrb[n * DH + 2 * tid]     - rwb[n * DH + 2 * tid];
        float d1 = rrb[n * DH + 2 * tid + 1] - rwb[n * DH + 2 * tid + 1];
        *(__half2*)(brh + 2 * tid) = __floats2half2_rn(d0, d1);
    }
    for (int f = tid; f < 64 * 16; f += 256) {
        int ti = f >> 4, d4 = (f & 15) * 4;
        float4 q  = *(const float4*)&g_heads[(size_t)((i0 + ti) * BSZ + b) * (3 * DM) + n * DH + d4];
        float4 wb = *(const float4*)&rwb[n * DH + d4];
        __half2 h0 = __floats2half2_rn(q.x + wb.x, q.y + wb.y);
        __half2 h1 = __floats2half2_rn(q.z + wb.z, q.w + wb.w);
        uint2 pk; pk.x = h2u(h0); pk.y = h2u(h1);
        *(uint2*)(Qsh + ti * H_STR + d4) = pk;
    }
    const float* rk_head = g_rk + n * DH;
    // pre-loop rel-pos rows (window-0 low half): all rows valid
    {
        const int mmin0 = QL - 64 - i0;
        for (int f = tid; f < 64 * 16; f += 256) {
            int ml = f >> 4, d4 = (f & 15) * 4;
            float4 rv = *(const float4*)&rk_head[(size_t)(mmin0 + ml) * DM + d4];
            __half2 h0 = __floats2half2_rn(rv.x, rv.y);
            __half2 h1 = __floats2half2_rn(rv.z, rv.w);
            uint2 pk; pk.x = h2u(h0); pk.y = h2u(h1);
            *(uint2*)(RVh + ml * H_STR + d4) = pk;
        }
    }
    __syncthreads();

    // ---- pre-loop G mma (f16): shifted store tj = ml - 63 + r, keep tj>=0 ----
    {
        float gc[4][4];
        #pragma unroll
        for (int nt = 0; nt < 4; nt++)
            #pragma unroll
            for (int q = 0; q < 4; q++) gc[nt][q] = 0.f;
        #pragma unroll
        for (int ks = 0; ks < 4; ks++) {
            const int k0 = ks * 16;
            uint32_t aq[4] = {
                *(const uint32_t*)(Qsh + (roff + g)     * H_STR + k0 + 2 * t),
                *(const uint32_t*)(Qsh + (roff + g + 8) * H_STR + k0 + 2 * t),
                *(const uint32_t*)(Qsh + (roff + g)     * H_STR + k0 + 2 * t + 8),
                *(const uint32_t*)(Qsh + (roff + g + 8) * H_STR + k0 + 2 * t + 8) };
            __half2 brA = *(const __half2*)(brh + k0 + 2 * t);
            __half2 brB = *(const __half2*)(brh + k0 + 2 * t + 8);
            uint32_t ar[4];
            { __half2 h = __hadd2(*(__half2*)&aq[0], brA); ar[0] = h2u(h); }
            { __half2 h = __hadd2(*(__half2*)&aq[1], brA); ar[1] = h2u(h); }
            { __half2 h = __hadd2(*(__half2*)&aq[2], brB); ar[2] = h2u(h); }
            { __half2 h = __hadd2(*(__half2*)&aq[3], brB); ar[3] = h2u(h); }
            #pragma unroll
            for (int nt = 0; nt < 4; nt++) {
                const __half* rp = RVh + (coff + nt * 8 + g) * H_STR + k0 + 2 * t;
                uint32_t bf[2] = { *(const uint32_t*)rp, *(const uint32_t*)(rp + 8) };
                MMA_F16(gc[nt], ar, bf);
            }
        }
        const int r0 = roff + g, r1 = r0 + 8;
        #pragma unroll
        for (int nt = 0; nt < 4; nt++) {
            const int mlb = coff + nt * 8 + 2 * t;
            int tja = mlb - 63 + r0;
            if (tja >= 0)     B0[r0 * F_STR + tja]     = gc[nt][0] * scale;
            if (tja + 1 >= 0) B0[r0 * F_STR + tja + 1] = gc[nt][1] * scale;
            int tjb = mlb - 63 + r1;
            if (tjb >= 0)     B0[r1 * F_STR + tjb]     = gc[nt][2] * scale;
            if (tjb + 1 >= 0) B0[r1 * F_STR + tjb + 1] = gc[nt][3] * scale;
        }
    }

    float* BDa = B0;
    float* BDb = B1;

    float O[4][4];
    #pragma unroll
    for (int nt = 0; nt < 4; nt++)
        #pragma unroll
        for (int q = 0; q < 4; q++) O[nt][q] = 0.f;
    float mrow = -INFINITY, lrow = 0.f;

    const int sm_ti = w * 8 + (l >> 2);
    const int sm_cb = (l & 3) * 16;

    for (int jt = 0; jt <= qt; jt++) {
        const int j0 = jt * 64;
        const int mbase = QL - i0 + j0;
        __syncthreads();   // prev iter PV done with Ph/RVh; softmax done with SP/BD

        // ---- fill K (half) and Rs (half, high-half rel-pos rows) ----
        for (int f = tid; f < 64 * 16; f += 256) {
            int tj = f >> 4, d4 = (f & 15) * 4;
            size_t base = (size_t)((j0 + tj) * BSZ + b) * (3 * DM) + n * DH + d4;
            float4 kv = *(const float4*)&g_heads[base + DM];
            __half2 h0 = __floats2half2_rn(kv.x, kv.y);
            __half2 h1 = __floats2half2_rn(kv.z, kv.w);
            uint2 pk; pk.x = h2u(h0); pk.y = h2u(h1);
            *(uint2*)(Ksh + tj * H_STR + d4) = pk;

            int m = mbase + tj;
            uint2 pr; pr.x = 0u; pr.y = 0u;
            if (m < QL) {
                float4 rv = *(const float4*)&rk_head[(size_t)m * DM + d4];
                __half2 r0h = __floats2half2_rn(rv.x, rv.y);
                __half2 r1h = __floats2half2_rn(rv.z, rv.w);
                pr.x = h2u(r0h); pr.y = h2u(r1h);
            }
            *(uint2*)(RVh + tj * H_STR + d4) = pr;
        }
        __syncthreads();

        // ---- S + Gnew mma (f16, k=16 per step) ----
        {
            float sc[4][4], gc[4][4];
            #pragma unroll
            for (int nt = 0; nt < 4; nt++)
                #pragma unroll
                for (int q = 0; q < 4; q++) { sc[nt][q] = 0.f; gc[nt][q] = 0.f; }

            #pragma unroll
            for (int ks = 0; ks < 4; ks++) {
                const int k0 = ks * 16;
                uint32_t aw[4] = {
                    *(const uint32_t*)(Qsh + (roff + g)     * H_STR + k0 + 2 * t),
                    *(const uint32_t*)(Qsh + (roff + g + 8) * H_STR + k0 + 2 * t),
                    *(const uint32_t*)(Qsh + (roff + g)     * H_STR + k0 + 2 * t + 8),
                    *(const uint32_t*)(Qsh + (roff + g + 8) * H_STR + k0 + 2 * t + 8) };
                __half2 brA = *(const __half2*)(brh + k0 + 2 * t);
                __half2 brB = *(const __half2*)(brh + k0 + 2 * t + 8);
                uint32_t ar[4];
                { __half2 h = __hadd2(*(__half2*)&aw[0], brA); ar[0] = h2u(h); }
                { __half2 h = __hadd2(*(__half2*)&aw[1], brA); ar[1] = h2u(h); }
                { __half2 h = __hadd2(*(__half2*)&aw[2], brB); ar[2] = h2u(h); }
                { __half2 h = __hadd2(*(__half2*)&aw[3], brB); ar[3] = h2u(h); }
                #pragma unroll
                for (int nt = 0; nt < 4; nt++) {
                    const __half* kp = Ksh + (coff + nt * 8 + g) * H_STR + k0 + 2 * t;
                    uint32_t bfk[2] = { *(const uint32_t*)kp, *(const uint32_t*)(kp + 8) };
                    MMA_F16(sc[nt], aw, bfk);
                    const __half* rp = RVh + (coff + nt * 8 + g) * H_STR + k0 + 2 * t;
                    uint32_t bfr[2] = { *(const uint32_t*)rp, *(const uint32_t*)(rp + 8) };
                    MMA_F16(gc[nt], ar, bfr);
                }
            }
            // S store (f32, unshifted)
            #pragma unroll
            for (int nt = 0; nt < 4; nt++) {
                float* ps = SP + (roff + g) * F_STR + coff + nt * 8 + 2 * t;
                ps[0] = sc[nt][0] * scale; ps[1] = sc[nt][1] * scale;
                ps[8 * F_STR] = sc[nt][2] * scale; ps[8 * F_STR + 1] = sc[nt][3] * scale;
            }
            // G store SHIFTED: (r, ml) -> tj = ml + r + 1; tj<64 -> BDa else BDb
            const int r0 = roff + g, r1 = r0 + 8;
            #pragma unroll
            for (int nt = 0; nt < 4; nt++) {
                const int mlb = coff + nt * 8 + 2 * t;
                int tja = mlb + r0 + 1;
                float* pa0 = ((tja     < 64) ? BDa : (BDb - 64)) + r0 * F_STR + tja;
                float* pa1 = ((tja + 1 < 64) ? BDa : (BDb - 64)) + r0 * F_STR + tja + 1;
                *pa0 = gc[nt][0] * scale;
                *pa1 = gc[nt][1] * scale;
                int tjb = mlb + r1 + 1;
                float* pb0 = ((tjb     < 64) ? BDa : (BDb - 64)) + r1 * F_STR + tjb;
                float* pb1 = ((tjb + 1 < 64) ? BDa : (BDb - 64)) + r1 * F_STR + tjb + 1;
                *pb0 = gc[nt][2] * scale;
                *pb1 = gc[nt][3] * scale;
            }
        }
        __syncthreads();   // Rs dead; SP/BD valid

        // ---- refill RVh as TRANSPOSED V: Vt[d][tj] (half2 over tj pairs) ----
        for (int f = tid; f < 512; f += 256) {
            int pr_ = f >> 4;            // tj pair index 0..31
            int d4  = (f & 15) * 4;      // d base 0..60
            int tj  = pr_ * 2;
            size_t base0 = (size_t)((j0 + tj) * BSZ + b) * (3 * DM) + n * DH + 2 * DM + d4;
            size_t base1 = (size_t)((j0 + tj + 1) * BSZ + b) * (3 * DM) + n * DH + 2 * DM + d4;
            float4 v0 = *(const float4*)&g_heads[base0];
            float4 v1 = *(const float4*)&g_heads[base1];
            *(__half2*)(RVh + (d4 + 0) * H_STR + tj) = __floats2half2_rn(v0.x, v1.x);
            *(__half2*)(RVh + (d4 + 1) * H_STR + tj) = __floats2half2_rn(v0.y, v1.y);
            *(__half2*)(RVh + (d4 + 2) * H_STR + tj) = __floats2half2_rn(v0.z, v1.z);
            *(__half2*)(RVh + (d4 + 3) * H_STR + tj) = __floats2half2_rn(v0.w, v1.w);
        }

        // ---- online softmax: 4 lanes per row, 16 cols per lane ----
        {
            const bool diag = (jt == qt);
            float sv[16];
            const float* sp = SP  + sm_ti * F_STR + sm_cb;
            const float* bp = BDa + sm_ti * F_STR + sm_cb;
            #pragma unroll
            for (int k = 0; k < 4; k++) {
                float4 s4 = *(const float4*)(sp + 4 * k);
                float4 g4 = *(const float4*)(bp + 4 * k);
                sv[4 * k + 0] = s4.x + g4.x;
                sv[4 * k + 1] = s4.y + g4.y;
                sv[4 * k + 2] = s4.z + g4.z;
                sv[4 * k + 3] = s4.w + g4.w;
            }
            if (diag) {
                #pragma unroll
                for (int c = 0; c < 16; c++)
                    if (sm_cb + c > sm_ti) sv[c] = -INFINITY;
            }
            float rm = sv[0];
            #pragma unroll
            for (int c = 1; c < 16; c++) rm = fmaxf(rm, sv[c]);
            rm = fmaxf(rm, __shfl_xor_sync(0xffffffffu, rm, 1));
            rm = fmaxf(rm, __shfl_xor_sync(0xffffffffu, rm, 2));
            float mnew = fmaxf(mrow, rm);
            float corr = __expf(mrow - mnew);
            float rs = 0.f;
            #pragma unroll
            for (int c = 0; c < 16; c++) {
                sv[c] = __expf(sv[c] - mnew);
                rs += sv[c];
            }
            rs += __shfl_xor_sync(0xffffffffu, rs, 1);
            rs += __shfl_xor_sync(0xffffffffu, rs, 2);
            lrow = lrow * corr + rs;
            mrow = mnew;
            __half* pp = Ph + sm_ti * H_STR + sm_cb;
            #pragma unroll
            for (int k = 0; k < 8; k++)
                *(__half2*)(pp + 2 * k) = __floats2half2_rn(sv[2 * k], sv[2 * k + 1]);
            if ((l & 3) == 0) corr_s[sm_ti] = corr;
        }
        __syncthreads();   // P (half) + Vt both ready

        // ---- O = O*corr + P @ V (f16 mma, k=16) ----
        {
            float c0 = corr_s[roff + g], c1 = corr_s[roff + g + 8];
            #pragma unroll
            for (int nt = 0; nt < 4; nt++) {
                O[nt][0] *= c0; O[nt][1] *= c0;
                O[nt][2] *= c1; O[nt][3] *= c1;
            }
        }
        #pragma unroll
        for (int ks = 0; ks < 4; ks++) {
            const int k0 = ks * 16;
            uint32_t ap[4] = {
                *(const uint32_t*)(Ph + (roff + g)     * H_STR + k0 + 2 * t),
                *(const uint32_t*)(Ph + (roff + g + 8) * H_STR + k0 + 2 * t),
                *(const uint32_t*)(Ph + (roff + g)     * H_STR + k0 + 2 * t + 8),
                *(const uint32_t*)(Ph + (roff + g + 8) * H_STR + k0 + 2 * t + 8) };
            #pragma unroll
            for (int nt = 0; nt < 4; nt++) {
                const __half* vp = RVh + (coff + nt * 8 + g) * H_STR + k0 + 2 * t;
                uint32_t bf[2] = { *(const uint32_t*)vp, *(const uint32_t*)(vp + 8) };
                MMA_F16(O[nt], ap, bf);
            }
        }

        float* tmp = BDa; BDa = BDb; BDb = tmp;
    }

    // ---- final normalization + store ----
    if ((l & 3) == 0) linv_s[sm_ti] = 1.f / lrow;
    __syncthreads();

    #pragma unroll
    for (int nt = 0; nt < 4; nt++) {
        const int col = n * DH + coff + nt * 8 + 2 * t;
        const int r0 = roff + g, r1 = roff + g + 8;
        const float li0 = linv_s[r0], li1 = linv_s[r1];
        size_t ro0 = (size_t)((i0 + r0) * BSZ + b) * DM;
        size_t ro1 = (size_t)((i0 + r1) * BSZ + b) * DM;
        float2 o0 = make_float2(O[nt][0] * li0, O[nt][1] * li0);
        float2 o1 = make_float2(O[nt][2] * li1, O[nt][3] * li1);
        *(float2*)&g_attnvec[ro0 + col] = o0;
        *(float2*)&g_attnvec[ro1 + col] = o1;
    }
}

// ---------------------------------------------------------------------------
// Residual add (+optional bias) + LayerNorm, one row (1024) per block.
// ---------------------------------------------------------------------------
__global__ void __launch_bounds__(256)
ln_kernel(const float* __restrict__ resid, const float* __restrict__ y,
          const float* __restrict__ bias, const float* __restrict__ gam,
          const float* __restrict__ bet, float* __restrict__ out)
{
    const int row = blockIdx.x;
    const int tid = threadIdx.x;
    __shared__ float buf[DM];
    __shared__ float red[8];

    float lsum = 0.f;
    for (int d = tid; d < DM; d += 256) {
        float v = resid[(long)row * DM + d] + y[(long)row * DM + d];
        if (bias) v += bias[d];
        buf[d] = v;
        lsum += v;
    }
    #pragma unroll
    for (int off = 16; off; off >>= 1) lsum += __shfl_xor_sync(0xffffffffu, lsum, off);
    if ((tid & 31) == 0) red[tid >> 5] = lsum;
    __syncthreads();
    float tot = 0.f;
    #pragma unroll
    for (int i = 0; i < 8; i++) tot += red[i];
    const float mean = tot * (1.f / DM);
    __syncthreads();

    float lv = 0.f;
    for (int d = tid; d < DM; d += 256) {
        float t = buf[d] - mean;
        lv += t * t;
    }
    #pragma unroll
    for (int off = 16; off; off >>= 1) lv += __shfl_xor_sync(0xffffffffu, lv, off);
    if ((tid & 31) == 0) red[tid >> 5] = lv;
    __syncthreads();
    float vtot = 0.f;
    #pragma unroll
    for (int i = 0; i < 8; i++) vtot += red[i];
    const float inv = rsqrtf(vtot * (1.f / DM) + 1e-5f);

    for (int d = tid; d < DM; d += 256)
        out[(long)row * DM + d] = (buf[d] - mean) * inv * gam[d] + bet[d];
}

// ---------------------------------------------------------------------------
// Host launch
// ---------------------------------------------------------------------------
extern "C" void kernel_launch(void* const* d_in, const int* in_sizes, int n_in,
                              void* d_out, int out_size)
{
    const float* w      = (const float*)d_in[0];
    const float* r      = (const float*)d_in[1];
    const float* rwb    = (const float*)d_in[2];
    const float* rrb    = (const float*)d_in[3];
    // d_in[4] = attn_mask (causal triu, implicit)
    const float* qkv_w  = (const float*)d_in[5];
    const float* rnet_w = (const float*)d_in[6];
    const float* o_w    = (const float*)d_in[7];
    const float* ln1_g  = (const float*)d_in[8];
    const float* ln1_b  = (const float*)d_in[9];
    const float* ffn_w1 = (const float*)d_in[10];
    const float* ffn_b1 = (const float*)d_in[11];
    const float* ffn_w2 = (const float*)d_in[12];
    const float* ffn_b2 = (const float*)d_in[13];
    const float* ln2_g  = (const float*)d_in[14];
    const float* ln2_b  = (const float*)d_in[15];

    float *heads, *rk, *attnvec, *attnout, *x, *h, *core;
    cudaGetSymbolAddress((void**)&heads,   g_heads);
    cudaGetSymbolAddress((void**)&rk,      g_rk);
    cudaGetSymbolAddress((void**)&attnvec, g_attnvec);
    cudaGetSymbolAddress((void**)&attnout, g_attnout);
    cudaGetSymbolAddress((void**)&x,       g_x);
    cudaGetSymbolAddress((void**)&h,       g_h);
    cudaGetSymbolAddress((void**)&core,    g_core);

    // 1) qkv projection                                   (launch idx 0)
    gemm_tf32<0><<<dim3(3 * DM / 128, NTOK / 128), 256>>>(w, qkv_w, heads, nullptr,
                                                          NTOK, 3 * DM, DM);
    // 2) r_k                                              (launch idx 1)
    gemm_tf32<0><<<dim3(DM / 128, QL / 128), 256>>>(r, rnet_w, rk, nullptr,
                                                    QL, DM, DM);
    // 3) one pad (idx 2) -> attention at idx 3 = ncu capture slot
    nop_kernel<<<1, 32>>>();
    // 4) attention (fp16 mma flash)                       (launch idx 3)
    {
        cudaFuncSetAttribute(attn_mma_kernel,
                             cudaFuncAttributeMaxDynamicSharedMemorySize, SMEM_ATT);
        attn_mma_kernel<<<dim3(QL / 64, NH, BSZ), 256, SMEM_ATT>>>(rwb, rrb);
    }
    // 5) o projection
    gemm_tf32<0><<<dim3(DM / 128, NTOK / 128), 256>>>(attnvec, o_w, attnout, nullptr,
                                                      NTOK, DM, DM);
    // 6) x = LN(w + attn_out)
    ln_kernel<<<NTOK, 256>>>(w, attnout, nullptr, ln1_g, ln1_b, x);
    // 7) h = relu(x @ ffn_w1 + b1)
    gemm_tf32<1><<<dim3(DI / 128, NTOK / 128), 256>>>(x, ffn_w1, h, ffn_b1,
                                                      NTOK, DI, DM);
    // 8) core = h @ ffn_w2
    gemm_tf32<0><<<dim3(DM / 128, NTOK / 128), 256>>>(h, ffn_w2, core, nullptr,
                                                      NTOK, DM, DI);
    // 9) out = LN(x + core + b2)
    ln_kernel<<<NTOK, 256>>>(x, core, ffn_b2, ln2_g, ln2_b, (float*)d_out);
}

// round 16
// speedup vs baseline: 1.5201x; 1.5201x over previous
#include <cuda_runtime.h>
#include <cuda_fp16.h>
#include <math.h>
#include <stdint.h>

// ---------------------------------------------------------------------------
// Problem constants
// ---------------------------------------------------------------------------
#define QL 2048
#define BSZ 2
#define DM 1024
#define NH 16
#define DH 64
#define DI 4096
#define NTOK (QL*BSZ)

// ---------------------------------------------------------------------------
// Scratch (device globals; no allocation allowed)
// ---------------------------------------------------------------------------
__device__ float g_heads[NTOK * 3 * DM];
__device__ float g_rk[QL * DM];
__device__ float g_attnvec[NTOK * DM];
__device__ float g_attnout[NTOK * DM];
__device__ float g_x[NTOK * DM];
__device__ float g_h[NTOK * DI];
__device__ float g_core[NTOK * DM];

// ---------------------------------------------------------------------------
// helpers
// ---------------------------------------------------------------------------
__device__ __forceinline__ float to_tf32(float v) {
    uint32_t u;
    asm("cvt.rna.tf32.f32 %0, %1;" : "=r"(u) : "f"(v));
    return __uint_as_float(u);
}

#define MMA_TF32(d, a, b)                                                      \
    asm volatile(                                                              \
        "mma.sync.aligned.m16n8k8.row.col.f32.tf32.tf32.f32 "                  \
        "{%0,%1,%2,%3},{%4,%5,%6,%7},{%8,%9},{%0,%1,%2,%3};\n"                 \
        : "+f"(d[0]), "+f"(d[1]), "+f"(d[2]), "+f"(d[3])                       \
        : "r"(a[0]), "r"(a[1]), "r"(a[2]), "r"(a[3]), "r"(b[0]), "r"(b[1]))

#define MMA_F16(d, a, b)                                                       \
    asm volatile(                                                              \
        "mma.sync.aligned.m16n8k16.row.col.f32.f16.f16.f32 "                   \
        "{%0,%1,%2,%3},{%4,%5,%6,%7},{%8,%9},{%0,%1,%2,%3};\n"                 \
        : "+f"(d[0]), "+f"(d[1]), "+f"(d[2]), "+f"(d[3])                       \
        : "r"(a[0]), "r"(a[1]), "r"(a[2]), "r"(a[3]), "r"(b[0]), "r"(b[1]))

__device__ __forceinline__ uint32_t h2u(__half2 h) { return *(uint32_t*)&h; }

// ---------------------------------------------------------------------------
// Pad kernel: ncu capture slot = launch index 3 (confirmed R12-R15).
// ---------------------------------------------------------------------------
__global__ void nop_kernel() {}

// ---------------------------------------------------------------------------
// Generic tf32 GEMM (unchanged, known-good)
// ---------------------------------------------------------------------------
template <int EPI>
__global__ void __launch_bounds__(256)
gemm_tf32(const float* __restrict__ A, const float* __restrict__ B,
          float* __restrict__ C, const float* __restrict__ bias,
          int M, int N, int K)
{
    const int bm = blockIdx.y * 128;
    const int bn = blockIdx.x * 128;

    __shared__ float As[128 * 36];
    __shared__ float Bs[32 * 136];

    const int tid = threadIdx.x;
    const int w   = tid >> 5;
    const int l   = tid & 31;
    const int g   = l >> 2;
    const int t   = l & 3;
    const int wm  = (w & 1) * 64;
    const int wn  = (w >> 1) * 32;

    float c[4][4][4];
    #pragma unroll
    for (int mt = 0; mt < 4; mt++)
        #pragma unroll
        for (int nt = 0; nt < 4; nt++)
            #pragma unroll
            for (int q = 0; q < 4; q++) c[mt][nt][q] = 0.f;

    float4 ra[4], rb[4];
    const int KT = K / 32;

    #define LOAD_G(kt)                                                         \
        {                                                                      \
            const float* Ap = A + (long)bm * K + (kt) * 32;                    \
            _Pragma("unroll")                                                  \
            for (int it = 0; it < 4; it++) {                                   \
                int f = tid + it * 256;                                        \
                int rr = f >> 3, c4 = f & 7;                                   \
                ra[it] = *(const float4*)(Ap + (long)rr * K + c4 * 4);         \
            }                                                                  \
            const float* Bp = B + (long)(kt) * 32 * N + bn;                    \
            _Pragma("unroll")                                                  \
            for (int it = 0; it < 4; it++) {                                   \
                int f = tid + it * 256;                                        \
                int rr = f >> 5, c4 = f & 31;                                  \
                rb[it] = *(const float4*)(Bp + (long)rr * N + c4 * 4);         \
            }                                                                  \
        }

    #define STORE_S()                                                          \
        {                                                                      \
            _Pragma("unroll")                                                  \
            for (int it = 0; it < 4; it++) {                                   \
                int f = tid + it * 256;                                        \
                int rr = f >> 3, c4 = f & 7;                                   \
                float* p = As + rr * 36 + c4 * 4;                              \
                p[0] = to_tf32(ra[it].x); p[1] = to_tf32(ra[it].y);            \
                p[2] = to_tf32(ra[it].z); p[3] = to_tf32(ra[it].w);            \
            }                                                                  \
            _Pragma("unroll")                                                  \
            for (int it = 0; it < 4; it++) {                                   \
                int f = tid + it * 256;                                        \
                int rr = f >> 5, c4 = f & 31;                                  \
                float* p = Bs + rr * 136 + c4 * 4;                             \
                p[0] = to_tf32(rb[it].x); p[1] = to_tf32(rb[it].y);            \
                p[2] = to_tf32(rb[it].z); p[3] = to_tf32(rb[it].w);            \
            }                                                                  \
        }

    LOAD_G(0);
    STORE_S();
    __syncthreads();

    for (int kt = 0; kt < KT; kt++) {
        if (kt + 1 < KT) LOAD_G(kt + 1);

        #pragma unroll
        for (int ks = 0; ks < 4; ks++) {
            uint32_t af[4][4], bf[4][2];
            #pragma unroll
            for (int mt = 0; mt < 4; mt++) {
                const float* ap = As + (wm + mt * 16) * 36 + ks * 8;
                af[mt][0] = __float_as_uint(ap[g * 36 + t]);
                af[mt][1] = __float_as_uint(ap[(g + 8) * 36 + t]);
                af[mt][2] = __float_as_uint(ap[g * 36 + t + 4]);
                af[mt][3] = __float_as_uint(ap[(g + 8) * 36 + t + 4]);
            }
            #pragma unroll
            for (int nt = 0; nt < 4; nt++) {
                const float* bp = Bs + (ks * 8) * 136 + wn + nt * 8;
                bf[nt][0] = __float_as_uint(bp[t * 136 + g]);
                bf[nt][1] = __float_as_uint(bp[(t + 4) * 136 + g]);
            }
            #pragma unroll
            for (int mt = 0; mt < 4; mt++)
                #pragma unroll
                for (int nt = 0; nt < 4; nt++)
                    MMA_TF32(c[mt][nt], af[mt], bf[nt]);
        }

        __syncthreads();
        if (kt + 1 < KT) {
            STORE_S();
            __syncthreads();
        }
    }

    #pragma unroll
    for (int mt = 0; mt < 4; mt++) {
        #pragma unroll
        for (int nt = 0; nt < 4; nt++) {
            int row0 = bm + wm + mt * 16 + g;
            int col  = bn + wn + nt * 8 + 2 * t;
            float v0 = c[mt][nt][0], v1 = c[mt][nt][1];
            float v2 = c[mt][nt][2], v3 = c[mt][nt][3];
            if (EPI == 1) {
                float b0 = bias[col], b1 = bias[col + 1];
                v0 = fmaxf(v0 + b0, 0.f); v1 = fmaxf(v1 + b1, 0.f);
                v2 = fmaxf(v2 + b0, 0.f); v3 = fmaxf(v3 + b1, 0.f);
            }
            float2 p01 = make_float2(v0, v1);
            float2 p23 = make_float2(v2, v3);
            *(float2*)(C + (long)row0 * N + col)       = p01;
            *(float2*)(C + (long)(row0 + 8) * N + col) = p23;
        }
    }
    #undef LOAD_G
    #undef STORE_S
}

// ---------------------------------------------------------------------------
// MMA flash causal rel-attention, v7 (fp16 operands, f32 accumulate).
// RESUBMITTED byte-identical from R15: profiled 516us (best) but the R15
// total regressed in a pattern matching the R5 DVFS-throttle precedent
// (same-binary GEMM 81->129us). This run is the clean A/B: if total lands
// ~1450 the throttle hypothesis is confirmed and fp16 is the new base;
// if it regresses again, fp16 has a real replay-path cost -> revert.
// ---------------------------------------------------------------------------
#define H_STR 72       // half stride: 36 banks -> frag banks (4g+t)%32
#define F_STR 68       // f32 stride for S/BD

#define QSH_OFF   0
#define KSH_OFF   9216
#define RVH_OFF   18432
#define PH_OFF    27648
#define SP_OFF    36864
#define B0_OFF    54272
#define B1_OFF    71680
#define BRH_OFF   89088
#define CORR_OFF  89216
#define LINV_OFF  89472
#define SMEM_ATT  89728

__global__ void __launch_bounds__(256, 2)
attn_mma_kernel(const float* __restrict__ rwb, const float* __restrict__ rrb)
{
    extern __shared__ char smb[];
    __half* Qsh = (__half*)(smb + QSH_OFF);
    __half* Ksh = (__half*)(smb + KSH_OFF);
    __half* RVh = (__half*)(smb + RVH_OFF);
    __half* Ph  = (__half*)(smb + PH_OFF);
    float*  SP  = (float*)(smb + SP_OFF);
    float*  B0  = (float*)(smb + B0_OFF);
    float*  B1  = (float*)(smb + B1_OFF);
    __half* brh = (__half*)(smb + BRH_OFF);
    float*  corr_s = (float*)(smb + CORR_OFF);
    float*  linv_s = (float*)(smb + LINV_OFF);

    const int qt = 31 - (int)blockIdx.x;
    const int n  = blockIdx.y;
    const int b  = blockIdx.z;
    const int i0 = qt * 64;
    const int tid = threadIdx.x;
    const int w = tid >> 5, l = tid & 31;
    const int g = l >> 2, t = l & 3;
    const int roff = (w >> 1) * 16;
    const int coff = (w & 1) * 32;
    const float scale = 0.125f;

    // ---- prologue: delta bias (half) + QW tile (half) ----
    if (tid < 32) {
        float d0 = rrb[n * DH + 2 * tid]     - rwb[n * DH + 2 * tid];
        float d1 = rrb[n * DH + 2 * tid + 1] - rwb[n * DH + 2 * tid + 1];
        *(__half2*)(brh + 2 * tid) = __floats2half2_rn(d0, d1);
    }
    for (int f = tid; f < 64 * 16; f += 256) {
        int ti = f >> 4, d4 = (f & 15) * 4;
        float4 q  = *(const float4*)&g_heads[(size_t)((i0 + ti) * BSZ + b) * (3 * DM) + n * DH + d4];
        float4 wb = *(const float4*)&rwb[n * DH + d4];
        __half2 h0 = __floats2half2_rn(q.x + wb.x, q.y + wb.y);
        __half2 h1 = __floats2half2_rn(q.z + wb.z, q.w + wb.w);
        uint2 pk; pk.x = h2u(h0); pk.y = h2u(h1);
        *(uint2*)(Qsh + ti * H_STR + d4) = pk;
    }
    const float* rk_head = g_rk + n * DH;
    {
        const int mmin0 = QL - 64 - i0;
        for (int f = tid; f < 64 * 16; f += 256) {
            int ml = f >> 4, d4 = (f & 15) * 4;
            float4 rv = *(const float4*)&rk_head[(size_t)(mmin0 + ml) * DM + d4];
            __half2 h0 = __floats2half2_rn(rv.x, rv.y);
            __half2 h1 = __floats2half2_rn(rv.z, rv.w);
            uint2 pk; pk.x = h2u(h0); pk.y = h2u(h1);
            *(uint2*)(RVh + ml * H_STR + d4) = pk;
        }
    }
    __syncthreads();

    // ---- pre-loop G mma (f16): shifted store tj = ml - 63 + r, keep tj>=0 ----
    {
        float gc[4][4];
        #pragma unroll
        for (int nt = 0; nt < 4; nt++)
            #pragma unroll
            for (int q = 0; q < 4; q++) gc[nt][q] = 0.f;
        #pragma unroll
        for (int ks = 0; ks < 4; ks++) {
            const int k0 = ks * 16;
            uint32_t aq[4] = {
                *(const uint32_t*)(Qsh + (roff + g)     * H_STR + k0 + 2 * t),
                *(const uint32_t*)(Qsh + (roff + g + 8) * H_STR + k0 + 2 * t),
                *(const uint32_t*)(Qsh + (roff + g)     * H_STR + k0 + 2 * t + 8),
                *(const uint32_t*)(Qsh + (roff + g + 8) * H_STR + k0 + 2 * t + 8) };
            __half2 brA = *(const __half2*)(brh + k0 + 2 * t);
            __half2 brB = *(const __half2*)(brh + k0 + 2 * t + 8);
            uint32_t ar[4];
            { __half2 h = __hadd2(*(__half2*)&aq[0], brA); ar[0] = h2u(h); }
            { __half2 h = __hadd2(*(__half2*)&aq[1], brA); ar[1] = h2u(h); }
            { __half2 h = __hadd2(*(__half2*)&aq[2], brB); ar[2] = h2u(h); }
            { __half2 h = __hadd2(*(__half2*)&aq[3], brB); ar[3] = h2u(h); }
            #pragma unroll
            for (int nt = 0; nt < 4; nt++) {
                const __half* rp = RVh + (coff + nt * 8 + g) * H_STR + k0 + 2 * t;
                uint32_t bf[2] = { *(const uint32_t*)rp, *(const uint32_t*)(rp + 8) };
                MMA_F16(gc[nt], ar, bf);
            }
        }
        const int r0 = roff + g, r1 = r0 + 8;
        #pragma unroll
        for (int nt = 0; nt < 4; nt++) {
            const int mlb = coff + nt * 8 + 2 * t;
            int tja = mlb - 63 + r0;
            if (tja >= 0)     B0[r0 * F_STR + tja]     = gc[nt][0] * scale;
            if (tja + 1 >= 0) B0[r0 * F_STR + tja + 1] = gc[nt][1] * scale;
            int tjb = mlb - 63 + r1;
            if (tjb >= 0)     B0[r1 * F_STR + tjb]     = gc[nt][2] * scale;
            if (tjb + 1 >= 0) B0[r1 * F_STR + tjb + 1] = gc[nt][3] * scale;
        }
    }

    float* BDa = B0;
    float* BDb = B1;

    float O[4][4];
    #pragma unroll
    for (int nt = 0; nt < 4; nt++)
        #pragma unroll
        for (int q = 0; q < 4; q++) O[nt][q] = 0.f;
    float mrow = -INFINITY, lrow = 0.f;

    const int sm_ti = w * 8 + (l >> 2);
    const int sm_cb = (l & 3) * 16;

    for (int jt = 0; jt <= qt; jt++) {
        const int j0 = jt * 64;
        const int mbase = QL - i0 + j0;
        __syncthreads();

        // ---- fill K (half) and Rs (half, high-half rel-pos rows) ----
        for (int f = tid; f < 64 * 16; f += 256) {
            int tj = f >> 4, d4 = (f & 15) * 4;
            size_t base = (size_t)((j0 + tj) * BSZ + b) * (3 * DM) + n * DH + d4;
            float4 kv = *(const float4*)&g_heads[base + DM];
            __half2 h0 = __floats2half2_rn(kv.x, kv.y);
            __half2 h1 = __floats2half2_rn(kv.z, kv.w);
            uint2 pk; pk.x = h2u(h0); pk.y = h2u(h1);
            *(uint2*)(Ksh + tj * H_STR + d4) = pk;

            int m = mbase + tj;
            uint2 pr; pr.x = 0u; pr.y = 0u;
            if (m < QL) {
                float4 rv = *(const float4*)&rk_head[(size_t)m * DM + d4];
                __half2 r0h = __floats2half2_rn(rv.x, rv.y);
                __half2 r1h = __floats2half2_rn(rv.z, rv.w);
                pr.x = h2u(r0h); pr.y = h2u(r1h);
            }
            *(uint2*)(RVh + tj * H_STR + d4) = pr;
        }
        __syncthreads();

        // ---- S + Gnew mma (f16, k=16 per step) ----
        {
            float sc[4][4], gc[4][4];
            #pragma unroll
            for (int nt = 0; nt < 4; nt++)
                #pragma unroll
                for (int q = 0; q < 4; q++) { sc[nt][q] = 0.f; gc[nt][q] = 0.f; }

            #pragma unroll
            for (int ks = 0; ks < 4; ks++) {
                const int k0 = ks * 16;
                uint32_t aw[4] = {
                    *(const uint32_t*)(Qsh + (roff + g)     * H_STR + k0 + 2 * t),
                    *(const uint32_t*)(Qsh + (roff + g + 8) * H_STR + k0 + 2 * t),
                    *(const uint32_t*)(Qsh + (roff + g)     * H_STR + k0 + 2 * t + 8),
                    *(const uint32_t*)(Qsh + (roff + g + 8) * H_STR + k0 + 2 * t + 8) };
                __half2 brA = *(const __half2*)(brh + k0 + 2 * t);
                __half2 brB = *(const __half2*)(brh + k0 + 2 * t + 8);
                uint32_t ar[4];
                { __half2 h = __hadd2(*(__half2*)&aw[0], brA); ar[0] = h2u(h); }
                { __half2 h = __hadd2(*(__half2*)&aw[1], brA); ar[1] = h2u(h); }
                { __half2 h = __hadd2(*(__half2*)&aw[2], brB); ar[2] = h2u(h); }
                { __half2 h = __hadd2(*(__half2*)&aw[3], brB); ar[3] = h2u(h); }
                #pragma unroll
                for (int nt = 0; nt < 4; nt++) {
                    const __half* kp = Ksh + (coff + nt * 8 + g) * H_STR + k0 + 2 * t;
                    uint32_t bfk[2] = { *(const uint32_t*)kp, *(const uint32_t*)(kp + 8) };
                    MMA_F16(sc[nt], aw, bfk);
                    const __half* rp = RVh + (coff + nt * 8 + g) * H_STR + k0 + 2 * t;
                    uint32_t bfr[2] = { *(const uint32_t*)rp, *(const uint32_t*)(rp + 8) };
                    MMA_F16(gc[nt], ar, bfr);
                }
            }
            #pragma unroll
            for (int nt = 0; nt < 4; nt++) {
                float* ps = SP + (roff + g) * F_STR + coff + nt * 8 + 2 * t;
                ps[0] = sc[nt][0] * scale; ps[1] = sc[nt][1] * scale;
                ps[8 * F_STR] = sc[nt][2] * scale; ps[8 * F_STR + 1] = sc[nt][3] * scale;
            }
            const int r0 = roff + g, r1 = r0 + 8;
            #pragma unroll
            for (int nt = 0; nt < 4; nt++) {
                const int mlb = coff + nt * 8 + 2 * t;
                int tja = mlb + r0 + 1;
                float* pa0 = ((tja     < 64) ? BDa : (BDb - 64)) + r0 * F_STR + tja;
                float* pa1 = ((tja + 1 < 64) ? BDa : (BDb - 64)) + r0 * F_STR + tja + 1;
                *pa0 = gc[nt][0] * scale;
                *pa1 = gc[nt][1] * scale;
                int tjb = mlb + r1 + 1;
                float* pb0 = ((tjb     < 64) ? BDa : (BDb - 64)) + r1 * F_STR + tjb;
                float* pb1 = ((tjb + 1 < 64) ? BDa : (BDb - 64)) + r1 * F_STR + tjb + 1;
                *pb0 = gc[nt][2] * scale;
                *pb1 = gc[nt][3] * scale;
            }
        }
        __syncthreads();

        // ---- refill RVh as TRANSPOSED V: Vt[d][tj] (half2 over tj pairs) ----
        for (int f = tid; f < 512; f += 256) {
            int pr_ = f >> 4;
            int d4  = (f & 15) * 4;
            int tj  = pr_ * 2;
            size_t base0 = (size_t)((j0 + tj) * BSZ + b) * (3 * DM) + n * DH + 2 * DM + d4;
            size_t base1 = (size_t)((j0 + tj + 1) * BSZ + b) * (3 * DM) + n * DH + 2 * DM + d4;
            float4 v0 = *(const float4*)&g_heads[base0];
            float4 v1 = *(const float4*)&g_heads[base1];
            *(__half2*)(RVh + (d4 + 0) * H_STR + tj) = __floats2half2_rn(v0.x, v1.x);
            *(__half2*)(RVh + (d4 + 1) * H_STR + tj) = __floats2half2_rn(v0.y, v1.y);
            *(__half2*)(RVh + (d4 + 2) * H_STR + tj) = __floats2half2_rn(v0.z, v1.z);
            *(__half2*)(RVh + (d4 + 3) * H_STR + tj) = __floats2half2_rn(v0.w, v1.w);
        }

        // ---- online softmax: 4 lanes per row, 16 cols per lane ----
        {
            const bool diag = (jt == qt);
            float sv[16];
            const float* sp = SP  + sm_ti * F_STR + sm_cb;
            const float* bp = BDa + sm_ti * F_STR + sm_cb;
            #pragma unroll
            for (int k = 0; k < 4; k++) {
                float4 s4 = *(const float4*)(sp + 4 * k);
                float4 g4 = *(const float4*)(bp + 4 * k);
                sv[4 * k + 0] = s4.x + g4.x;
                sv[4 * k + 1] = s4.y + g4.y;
                sv[4 * k + 2] = s4.z + g4.z;
                sv[4 * k + 3] = s4.w + g4.w;
            }
            if (diag) {
                #pragma unroll
                for (int c = 0; c < 16; c++)
                    if (sm_cb + c > sm_ti) sv[c] = -INFINITY;
            }
            float rm = sv[0];
            #pragma unroll
            for (int c = 1; c < 16; c++) rm = fmaxf(rm, sv[c]);
            rm = fmaxf(rm, __shfl_xor_sync(0xffffffffu, rm, 1));
            rm = fmaxf(rm, __shfl_xor_sync(0xffffffffu, rm, 2));
            float mnew = fmaxf(mrow, rm);
            float corr = __expf(mrow - mnew);
            float rs = 0.f;
            #pragma unroll
            for (int c = 0; c < 16; c++) {
                sv[c] = __expf(sv[c] - mnew);
                rs += sv[c];
            }
            rs += __shfl_xor_sync(0xffffffffu, rs, 1);
            rs += __shfl_xor_sync(0xffffffffu, rs, 2);
            lrow = lrow * corr + rs;
            mrow = mnew;
            __half* pp = Ph + sm_ti * H_STR + sm_cb;
            #pragma unroll
            for (int k = 0; k < 8; k++)
                *(__half2*)(pp + 2 * k) = __floats2half2_rn(sv[2 * k], sv[2 * k + 1]);
            if ((l & 3) == 0) corr_s[sm_ti] = corr;
        }
        __syncthreads();

        // ---- O = O*corr + P @ V (f16 mma, k=16) ----
        {
            float c0 = corr_s[roff + g], c1 = corr_s[roff + g + 8];
            #pragma unroll
            for (int nt = 0; nt < 4; nt++) {
                O[nt][0] *= c0; O[nt][1] *= c0;
                O[nt][2] *= c1; O[nt][3] *= c1;
            }
        }
        #pragma unroll
        for (int ks = 0; ks < 4; ks++) {
            const int k0 = ks * 16;
            uint32_t ap[4] = {
                *(const uint32_t*)(Ph + (roff + g)     * H_STR + k0 + 2 * t),
                *(const uint32_t*)(Ph + (roff + g + 8) * H_STR + k0 + 2 * t),
                *(const uint32_t*)(Ph + (roff + g)     * H_STR + k0 + 2 * t + 8),
                *(const uint32_t*)(Ph + (roff + g + 8) * H_STR + k0 + 2 * t + 8) };
            #pragma unroll
            for (int nt = 0; nt < 4; nt++) {
                const __half* vp = RVh + (coff + nt * 8 + g) * H_STR + k0 + 2 * t;
                uint32_t bf[2] = { *(const uint32_t*)vp, *(const uint32_t*)(vp + 8) };
                MMA_F16(O[nt], ap, bf);
            }
        }

        float* tmp = BDa; BDa = BDb; BDb = tmp;
    }

    // ---- final normalization + store ----
    if ((l & 3) == 0) linv_s[sm_ti] = 1.f / lrow;
    __syncthreads();

    #pragma unroll
    for (int nt = 0; nt < 4; nt++) {
        const int col = n * DH + coff + nt * 8 + 2 * t;
        const int r0 = roff + g, r1 = roff + g + 8;
        const float li0 = linv_s[r0], li1 = linv_s[r1];
        size_t ro0 = (size_t)((i0 + r0) * BSZ + b) * DM;
        size_t ro1 = (size_t)((i0 + r1) * BSZ + b) * DM;
        float2 o0 = make_float2(O[nt][0] * li0, O[nt][1] * li0);
        float2 o1 = make_float2(O[nt][2] * li1, O[nt][3] * li1);
        *(float2*)&g_attnvec[ro0 + col] = o0;
        *(float2*)&g_attnvec[ro1 + col] = o1;
    }
}

// ---------------------------------------------------------------------------
// Residual add (+optional bias) + LayerNorm, one row (1024) per block.
// ---------------------------------------------------------------------------
__global__ void __launch_bounds__(256)
ln_kernel(const float* __restrict__ resid, const float* __restrict__ y,
          const float* __restrict__ bias, const float* __restrict__ gam,
          const float* __restrict__ bet, float* __restrict__ out)
{
    const int row = blockIdx.x;
    const int tid = threadIdx.x;
    __shared__ float buf[DM];
    __shared__ float red[8];

    float lsum = 0.f;
    for (int d = tid; d < DM; d += 256) {
        float v = resid[(long)row * DM + d] + y[(long)row * DM + d];
        if (bias) v += bias[d];
        buf[d] = v;
        lsum += v;
    }
    #pragma unroll
    for (int off = 16; off; off >>= 1) lsum += __shfl_xor_sync(0xffffffffu, lsum, off);
    if ((tid & 31) == 0) red[tid >> 5] = lsum;
    __syncthreads();
    float tot = 0.f;
    #pragma unroll
    for (int i = 0; i < 8; i++) tot += red[i];
    const float mean = tot * (1.f / DM);
    __syncthreads();

    float lv = 0.f;
    for (int d = tid; d < DM; d += 256) {
        float t = buf[d] - mean;
        lv += t * t;
    }
    #pragma unroll
    for (int off = 16; off; off >>= 1) lv += __shfl_xor_sync(0xffffffffu, lv, off);
    if ((tid & 31) == 0) red[tid >> 5] = lv;
    __syncthreads();
    float vtot = 0.f;
    #pragma unroll
    for (int i = 0; i < 8; i++) vtot += red[i];
    const float inv = rsqrtf(vtot * (1.f / DM) + 1e-5f);

    for (int d = tid; d < DM; d += 256)
        out[(long)row * DM + d] = (buf[d] - mean) * inv * gam[d] + bet[d];
}

// ---------------------------------------------------------------------------
// Host launch
// ---------------------------------------------------------------------------
extern "C" void kernel_launch(void* const* d_in, const int* in_sizes, int n_in,
                              void* d_out, int out_size)
{
    const float* w      = (const float*)d_in[0];
    const float* r      = (const float*)d_in[1];
    const float* rwb    = (const float*)d_in[2];
    const float* rrb    = (const float*)d_in[3];
    // d_in[4] = attn_mask (causal triu, implicit)
    const float* qkv_w  = (const float*)d_in[5];
    const float* rnet_w = (const float*)d_in[6];
    const float* o_w    = (const float*)d_in[7];
    const float* ln1_g  = (const float*)d_in[8];
    const float* ln1_b  = (const float*)d_in[9];
    const float* ffn_w1 = (const float*)d_in[10];
    const float* ffn_b1 = (const float*)d_in[11];
    const float* ffn_w2 = (const float*)d_in[12];
    const float* ffn_b2 = (const float*)d_in[13];
    const float* ln2_g  = (const float*)d_in[14];
    const float* ln2_b  = (const float*)d_in[15];

    float *heads, *rk, *attnvec, *attnout, *x, *h, *core;
    cudaGetSymbolAddress((void**)&heads,   g_heads);
    cudaGetSymbolAddress((void**)&rk,      g_rk);
    cudaGetSymbolAddress((void**)&attnvec, g_attnvec);
    cudaGetSymbolAddress((void**)&attnout, g_attnout);
    cudaGetSymbolAddress((void**)&x,       g_x);
    cudaGetSymbolAddress((void**)&h,       g_h);
    cudaGetSymbolAddress((void**)&core,    g_core);

    // 1) qkv projection                                   (launch idx 0)
    gemm_tf32<0><<<dim3(3 * DM / 128, NTOK / 128), 256>>>(w, qkv_w, heads, nullptr,
                                                          NTOK, 3 * DM, DM);
    // 2) r_k                                              (launch idx 1)
    gemm_tf32<0><<<dim3(DM / 128, QL / 128), 256>>>(r, rnet_w, rk, nullptr,
                                                    QL, DM, DM);
    // 3) one pad (idx 2) -> attention at idx 3 = ncu capture slot
    nop_kernel<<<1, 32>>>();
    // 4) attention (fp16 mma flash)                       (launch idx 3)
    {
        cudaFuncSetAttribute(attn_mma_kernel,
                             cudaFuncAttributeMaxDynamicSharedMemorySize, SMEM_ATT);
        attn_mma_kernel<<<dim3(QL / 64, NH, BSZ), 256, SMEM_ATT>>>(rwb, rrb);
    }
    // 5) o projection
    gemm_tf32<0><<<dim3(DM / 128, NTOK / 128), 256>>>(attnvec, o_w, attnout, nullptr,
                                                      NTOK, DM, DM);
    // 6) x = LN(w + attn_out)
    ln_kernel<<<NTOK, 256>>>(w, attnout, nullptr, ln1_g, ln1_b, x);
    // 7) h = relu(x @ ffn_w1 + b1)
    gemm_tf32<1><<<dim3(DI / 128, NTOK / 128), 256>>>(x, ffn_w1, h, ffn_b1,
                                                      NTOK, DI, DM);
    // 8) core = h @ ffn_w2
    gemm_tf32<0><<<dim3(DM / 128, NTOK / 128), 256>>>(h, ffn_w2, core, nullptr,
                                                      NTOK, DM, DI);
    // 9) out = LN(x + core + b2)
    ln_kernel<<<NTOK, 256>>>(x, core, ffn_b2, ln2_g, ln2_b, (float*)d_out);
}

// round 17
// speedup vs baseline: 2.1862x; 1.4382x over previous
#include <cuda_runtime.h>
#include <cuda_fp16.h>
#include <math.h>
#include <stdint.h>

// ---------------------------------------------------------------------------
// Problem constants
// ---------------------------------------------------------------------------
#define QL 2048
#define BSZ 2
#define DM 1024
#define NH 16
#define DH 64
#define DI 4096
#define NTOK (QL*BSZ)

// ---------------------------------------------------------------------------
// Scratch (device globals; no allocation allowed)
// ---------------------------------------------------------------------------
__device__ float g_heads[NTOK * 3 * DM];
__device__ float g_rk[QL * DM];
__device__ float g_attnvec[NTOK * DM];
__device__ float g_attnout[NTOK * DM];
__device__ float g_x[NTOK * DM];
__device__ float g_h[NTOK * DI];
__device__ float g_core[NTOK * DM];

// ---------------------------------------------------------------------------
// helpers
// ---------------------------------------------------------------------------
#define MMA_F16(d, a, b)                                                       \
    asm volatile(                                                              \
        "mma.sync.aligned.m16n8k16.row.col.f32.f16.f16.f32 "                   \
        "{%0,%1,%2,%3},{%4,%5,%6,%7},{%8,%9},{%0,%1,%2,%3};\n"                 \
        : "+f"(d[0]), "+f"(d[1]), "+f"(d[2]), "+f"(d[3])                       \
        : "r"(a[0]), "r"(a[1]), "r"(a[2]), "r"(a[3]), "r"(b[0]), "r"(b[1]))

#define LDSM_X4(r0, r1, r2, r3, addr)                                          \
    asm volatile("ldmatrix.sync.aligned.m8n8.x4.shared.b16 {%0,%1,%2,%3}, [%4];" \
        : "=r"(r0), "=r"(r1), "=r"(r2), "=r"(r3) : "r"(addr))

#define LDSM_X4T(r0, r1, r2, r3, addr)                                         \
    asm volatile("ldmatrix.sync.aligned.m8n8.x4.trans.shared.b16 {%0,%1,%2,%3}, [%4];" \
        : "=r"(r0), "=r"(r1), "=r"(r2), "=r"(r3) : "r"(addr))

__device__ __forceinline__ uint32_t h2u(__half2 h) { return *(uint32_t*)&h; }

// ---------------------------------------------------------------------------
// fp16 GEMM with ldmatrix: C[M,N] = A[M,K] @ B[K,N]  (+bias+relu per EPI)
// Tile 128x128x32, 256 threads, warp tile 64x32, fp32 accumulate.
// A in smem [m][k] stride 40 halves  (ldmatrix rows: banks 20r%32, distinct)
// B in smem [k][n] stride 136 halves (ldmatrix.trans rows: banks 4r, distinct)
// Per k-tile per warp: 12 ldmatrix + 32 HMMA.16816 (vs 96 LDS + 64 HMMA.1688).
// Packed-half prefetch regs (16) + 64 accum -> fits 2 CTAs/SM.
// ---------------------------------------------------------------------------
#define GA_STR 40
#define GB_STR 136

template <int EPI>
__global__ void __launch_bounds__(256, 2)
gemm_f16(const float* __restrict__ A, const float* __restrict__ B,
         float* __restrict__ C, const float* __restrict__ bias,
         int M, int N, int K)
{
    const int bm = blockIdx.y * 128;
    const int bn = blockIdx.x * 128;

    __shared__ __half As[128 * GA_STR];
    __shared__ __half Bs[32 * GB_STR];

    const int tid = threadIdx.x;
    const int w   = tid >> 5;
    const int l   = tid & 31;
    const int g   = l >> 2;
    const int t   = l & 3;
    const int wm  = (w & 1) * 64;
    const int wn  = (w >> 1) * 32;
    const int lm  = l & 15;          // ldmatrix row lane
    const int lh  = (l >> 4) << 3;   // ldmatrix col-half offset {0,8}

    float c[4][4][4];
    #pragma unroll
    for (int mt = 0; mt < 4; mt++)
        #pragma unroll
        for (int nt = 0; nt < 4; nt++)
            #pragma unroll
            for (int q = 0; q < 4; q++) c[mt][nt][q] = 0.f;

    uint2 ra2[4], rb2[4];
    const int KT = K / 32;

    const uint32_t as_u = (uint32_t)__cvta_generic_to_shared(As);
    const uint32_t bs_u = (uint32_t)__cvta_generic_to_shared(Bs);

    #define LOAD_G(kt)                                                         \
        {                                                                      \
            const float* Ap = A + (long)bm * K + (kt) * 32;                    \
            _Pragma("unroll")                                                  \
            for (int it = 0; it < 4; it++) {                                   \
                int f = tid + it * 256;                                        \
                int rr = f >> 3, c4 = f & 7;                                   \
                float4 v = *(const float4*)(Ap + (long)rr * K + c4 * 4);       \
                ra2[it].x = h2u(__floats2half2_rn(v.x, v.y));                  \
                ra2[it].y = h2u(__floats2half2_rn(v.z, v.w));                  \
            }                                                                  \
            const float* Bp = B + (long)(kt) * 32 * N + bn;                    \
            _Pragma("unroll")                                                  \
            for (int it = 0; it < 4; it++) {                                   \
                int f = tid + it * 256;                                        \
                int rr = f >> 5, c4 = f & 31;                                  \
                float4 v = *(const float4*)(Bp + (long)rr * N + c4 * 4);       \
                rb2[it].x = h2u(__floats2half2_rn(v.x, v.y));                  \
                rb2[it].y = h2u(__floats2half2_rn(v.z, v.w));                  \
            }                                                                  \
        }

    #define STORE_S()                                                          \
        {                                                                      \
            _Pragma("unroll")                                                  \
            for (int it = 0; it < 4; it++) {                                   \
                int f = tid + it * 256;                                        \
                int rr = f >> 3, c4 = f & 7;                                   \
                *(uint2*)(As + rr * GA_STR + c4 * 4) = ra2[it];                \
            }                                                                  \
            _Pragma("unroll")                                                  \
            for (int it = 0; it < 4; it++) {                                   \
                int f = tid + it * 256;                                        \
                int rr = f >> 5, c4 = f & 31;                                  \
                *(uint2*)(Bs + rr * GB_STR + c4 * 4) = rb2[it];                \
            }                                                                  \
        }

    LOAD_G(0);
    STORE_S();
    __syncthreads();

    for (int kt = 0; kt < KT; kt++) {
        if (kt + 1 < KT) LOAD_G(kt + 1);

        #pragma unroll
        for (int ks = 0; ks < 2; ks++) {
            const int k0 = ks * 16;
            uint32_t af[4][4], bf[4][2];
            #pragma unroll
            for (int mt = 0; mt < 4; mt++) {
                uint32_t aaddr = as_u +
                    (uint32_t)(((wm + mt * 16 + lm) * GA_STR + k0 + lh) * 2);
                LDSM_X4(af[mt][0], af[mt][1], af[mt][2], af[mt][3], aaddr);
            }
            #pragma unroll
            for (int np = 0; np < 2; np++) {
                uint32_t baddr = bs_u +
                    (uint32_t)(((k0 + lm) * GB_STR + wn + np * 16 + lh) * 2);
                LDSM_X4T(bf[2 * np][0], bf[2 * np][1],
                         bf[2 * np + 1][0], bf[2 * np + 1][1], baddr);
            }
            #pragma unroll
            for (int mt = 0; mt < 4; mt++)
                #pragma unroll
                for (int nt = 0; nt < 4; nt++)
                    MMA_F16(c[mt][nt], af[mt], bf[nt]);
        }

        __syncthreads();
        if (kt + 1 < KT) {
            STORE_S();
            __syncthreads();
        }
    }

    #pragma unroll
    for (int mt = 0; mt < 4; mt++) {
        #pragma unroll
        for (int nt = 0; nt < 4; nt++) {
            int row0 = bm + wm + mt * 16 + g;
            int col  = bn + wn + nt * 8 + 2 * t;
            float v0 = c[mt][nt][0], v1 = c[mt][nt][1];
            float v2 = c[mt][nt][2], v3 = c[mt][nt][3];
            if (EPI == 1) {
                float b0 = bias[col], b1 = bias[col + 1];
                v0 = fmaxf(v0 + b0, 0.f); v1 = fmaxf(v1 + b1, 0.f);
                v2 = fmaxf(v2 + b0, 0.f); v3 = fmaxf(v3 + b1, 0.f);
            }
            float2 p01 = make_float2(v0, v1);
            float2 p23 = make_float2(v2, v3);
            *(float2*)(C + (long)row0 * N + col)       = p01;
            *(float2*)(C + (long)(row0 + 8) * N + col) = p23;
        }
    }
    #undef LOAD_G
    #undef STORE_S
}

// ---------------------------------------------------------------------------
// MMA flash causal rel-attention, v7 (fp16 operands, f32 accumulate).
// UNCHANGED from R16 best (379us profiled).
// ---------------------------------------------------------------------------
#define H_STR 72
#define F_STR 68

#define QSH_OFF   0
#define KSH_OFF   9216
#define RVH_OFF   18432
#define PH_OFF    27648
#define SP_OFF    36864
#define B0_OFF    54272
#define B1_OFF    71680
#define BRH_OFF   89088
#define CORR_OFF  89216
#define LINV_OFF  89472
#define SMEM_ATT  89728

__global__ void __launch_bounds__(256, 2)
attn_mma_kernel(const float* __restrict__ rwb, const float* __restrict__ rrb)
{
    extern __shared__ char smb[];
    __half* Qsh = (__half*)(smb + QSH_OFF);
    __half* Ksh = (__half*)(smb + KSH_OFF);
    __half* RVh = (__half*)(smb + RVH_OFF);
    __half* Ph  = (__half*)(smb + PH_OFF);
    float*  SP  = (float*)(smb + SP_OFF);
    float*  B0  = (float*)(smb + B0_OFF);
    float*  B1  = (float*)(smb + B1_OFF);
    __half* brh = (__half*)(smb + BRH_OFF);
    float*  corr_s = (float*)(smb + CORR_OFF);
    float*  linv_s = (float*)(smb + LINV_OFF);

    const int qt = 31 - (int)blockIdx.x;
    const int n  = blockIdx.y;
    const int b  = blockIdx.z;
    const int i0 = qt * 64;
    const int tid = threadIdx.x;
    const int w = tid >> 5, l = tid & 31;
    const int g = l >> 2, t = l & 3;
    const int roff = (w >> 1) * 16;
    const int coff = (w & 1) * 32;
    const float scale = 0.125f;

    if (tid < 32) {
        float d0 = rrb[n * DH + 2 * tid]     - rwb[n * DH + 2 * tid];
        float d1 = rrb[n * DH + 2 * tid + 1] - rwb[n * DH + 2 * tid + 1];
        *(__half2*)(brh + 2 * tid) = __floats2half2_rn(d0, d1);
    }
    for (int f = tid; f < 64 * 16; f += 256) {
        int ti = f >> 4, d4 = (f & 15) * 4;
        float4 q  = *(const float4*)&g_heads[(size_t)((i0 + ti) * BSZ + b) * (3 * DM) + n * DH + d4];
        float4 wb = *(const float4*)&rwb[n * DH + d4];
        __half2 h0 = __floats2half2_rn(q.x + wb.x, q.y + wb.y);
        __half2 h1 = __floats2half2_rn(q.z + wb.z, q.w + wb.w);
        uint2 pk; pk.x = h2u(h0); pk.y = h2u(h1);
        *(uint2*)(Qsh + ti * H_STR + d4) = pk;
    }
    const float* rk_head = g_rk + n * DH;
    {
        const int mmin0 = QL - 64 - i0;
        for (int f = tid; f < 64 * 16; f += 256) {
            int ml = f >> 4, d4 = (f & 15) * 4;
            float4 rv = *(const float4*)&rk_head[(size_t)(mmin0 + ml) * DM + d4];
            __half2 h0 = __floats2half2_rn(rv.x, rv.y);
            __half2 h1 = __floats2half2_rn(rv.z, rv.w);
            uint2 pk; pk.x = h2u(h0); pk.y = h2u(h1);
            *(uint2*)(RVh + ml * H_STR + d4) = pk;
        }
    }
    __syncthreads();

    {
        float gc[4][4];
        #pragma unroll
        for (int nt = 0; nt < 4; nt++)
            #pragma unroll
            for (int q = 0; q < 4; q++) gc[nt][q] = 0.f;
        #pragma unroll
        for (int ks = 0; ks < 4; ks++) {
            const int k0 = ks * 16;
            uint32_t aq[4] = {
                *(const uint32_t*)(Qsh + (roff + g)     * H_STR + k0 + 2 * t),
                *(const uint32_t*)(Qsh + (roff + g + 8) * H_STR + k0 + 2 * t),
                *(const uint32_t*)(Qsh + (roff + g)     * H_STR + k0 + 2 * t + 8),
                *(const uint32_t*)(Qsh + (roff + g + 8) * H_STR + k0 + 2 * t + 8) };
            __half2 brA = *(const __half2*)(brh + k0 + 2 * t);
            __half2 brB = *(const __half2*)(brh + k0 + 2 * t + 8);
            uint32_t ar[4];
            { __half2 h = __hadd2(*(__half2*)&aq[0], brA); ar[0] = h2u(h); }
            { __half2 h = __hadd2(*(__half2*)&aq[1], brA); ar[1] = h2u(h); }
            { __half2 h = __hadd2(*(__half2*)&aq[2], brB); ar[2] = h2u(h); }
            { __half2 h = __hadd2(*(__half2*)&aq[3], brB); ar[3] = h2u(h); }
            #pragma unroll
            for (int nt = 0; nt < 4; nt++) {
                const __half* rp = RVh + (coff + nt * 8 + g) * H_STR + k0 + 2 * t;
                uint32_t bf[2] = { *(const uint32_t*)rp, *(const uint32_t*)(rp + 8) };
                MMA_F16(gc[nt], ar, bf);
            }
        }
        const int r0 = roff + g, r1 = r0 + 8;
        #pragma unroll
        for (int nt = 0; nt < 4; nt++) {
            const int mlb = coff + nt * 8 + 2 * t;
            int tja = mlb - 63 + r0;
            if (tja >= 0)     B0[r0 * F_STR + tja]     = gc[nt][0] * scale;
            if (tja + 1 >= 0) B0[r0 * F_STR + tja + 1] = gc[nt][1] * scale;
            int tjb = mlb - 63 + r1;
            if (tjb >= 0)     B0[r1 * F_STR + tjb]     = gc[nt][2] * scale;
            if (tjb + 1 >= 0) B0[r1 * F_STR + tjb + 1] = gc[nt][3] * scale;
        }
    }

    float* BDa = B0;
    float* BDb = B1;

    float O[4][4];
    #pragma unroll
    for (int nt = 0; nt < 4; nt++)
        #pragma unroll
        for (int q = 0; q < 4; q++) O[nt][q] = 0.f;
    float mrow = -INFINITY, lrow = 0.f;

    const int sm_ti = w * 8 + (l >> 2);
    const int sm_cb = (l & 3) * 16;

    for (int jt = 0; jt <= qt; jt++) {
        const int j0 = jt * 64;
        const int mbase = QL - i0 + j0;
        __syncthreads();

        for (int f = tid; f < 64 * 16; f += 256) {
            int tj = f >> 4, d4 = (f & 15) * 4;
            size_t base = (size_t)((j0 + tj) * BSZ + b) * (3 * DM) + n * DH + d4;
            float4 kv = *(const float4*)&g_heads[base + DM];
            __half2 h0 = __floats2half2_rn(kv.x, kv.y);
            __half2 h1 = __floats2half2_rn(kv.z, kv.w);
            uint2 pk; pk.x = h2u(h0); pk.y = h2u(h1);
            *(uint2*)(Ksh + tj * H_STR + d4) = pk;

            int m = mbase + tj;
            uint2 pr; pr.x = 0u; pr.y = 0u;
            if (m < QL) {
                float4 rv = *(const float4*)&rk_head[(size_t)m * DM + d4];
                __half2 r0h = __floats2half2_rn(rv.x, rv.y);
                __half2 r1h = __floats2half2_rn(rv.z, rv.w);
                pr.x = h2u(r0h); pr.y = h2u(r1h);
            }
            *(uint2*)(RVh + tj * H_STR + d4) = pr;
        }
        __syncthreads();

        {
            float sc[4][4], gc[4][4];
            #pragma unroll
            for (int nt = 0; nt < 4; nt++)
                #pragma unroll
                for (int q = 0; q < 4; q++) { sc[nt][q] = 0.f; gc[nt][q] = 0.f; }

            #pragma unroll
            for (int ks = 0; ks < 4; ks++) {
                const int k0 = ks * 16;
                uint32_t aw[4] = {
                    *(const uint32_t*)(Qsh + (roff + g)     * H_STR + k0 + 2 * t),
                    *(const uint32_t*)(Qsh + (roff + g + 8) * H_STR + k0 + 2 * t),
                    *(const uint32_t*)(Qsh + (roff + g)     * H_STR + k0 + 2 * t + 8),
                    *(const uint32_t*)(Qsh + (roff + g + 8) * H_STR + k0 + 2 * t + 8) };
                __half2 brA = *(const __half2*)(brh + k0 + 2 * t);
                __half2 brB = *(const __half2*)(brh + k0 + 2 * t + 8);
                uint32_t ar[4];
                { __half2 h = __hadd2(*(__half2*)&aw[0], brA); ar[0] = h2u(h); }
                { __half2 h = __hadd2(*(__half2*)&aw[1], brA); ar[1] = h2u(h); }
                { __half2 h = __hadd2(*(__half2*)&aw[2], brB); ar[2] = h2u(h); }
                { __half2 h = __hadd2(*(__half2*)&aw[3], brB); ar[3] = h2u(h); }
                #pragma unroll
                for (int nt = 0; nt < 4; nt++) {
                    const __half* kp = Ksh + (coff + nt * 8 + g) * H_STR + k0 + 2 * t;
                    uint32_t bfk[2] = { *(const uint32_t*)kp, *(const uint32_t*)(kp + 8) };
                    MMA_F16(sc[nt], aw, bfk);
                    const __half* rp = RVh + (coff + nt * 8 + g) * H_STR + k0 + 2 * t;
                    uint32_t bfr[2] = { *(const uint32_t*)rp, *(const uint32_t*)(rp + 8) };
                    MMA_F16(gc[nt], ar, bfr);
                }
            }
            #pragma unroll
            for (int nt = 0; nt < 4; nt++) {
                float* ps = SP + (roff + g) * F_STR + coff + nt * 8 + 2 * t;
                ps[0] = sc[nt][0] * scale; ps[1] = sc[nt][1] * scale;
                ps[8 * F_STR] = sc[nt][2] * scale; ps[8 * F_STR + 1] = sc[nt][3] * scale;
            }
            const int r0 = roff + g, r1 = r0 + 8;
            #pragma unroll
            for (int nt = 0; nt < 4; nt++) {
                const int mlb = coff + nt * 8 + 2 * t;
                int tja = mlb + r0 + 1;
                float* pa0 = ((tja     < 64) ? BDa : (BDb - 64)) + r0 * F_STR + tja;
                float* pa1 = ((tja + 1 < 64) ? BDa : (BDb - 64)) + r0 * F_STR + tja + 1;
                *pa0 = gc[nt][0] * scale;
                *pa1 = gc[nt][1] * scale;
                int tjb = mlb + r1 + 1;
                float* pb0 = ((tjb     < 64) ? BDa : (BDb - 64)) + r1 * F_STR + tjb;
                float* pb1 = ((tjb + 1 < 64) ? BDa : (BDb - 64)) + r1 * F_STR + tjb + 1;
                *pb0 = gc[nt][2] * scale;
                *pb1 = gc[nt][3] * scale;
            }
        }
        __syncthreads();

        for (int f = tid; f < 512; f += 256) {
            int pr_ = f >> 4;
            int d4  = (f & 15) * 4;
            int tj  = pr_ * 2;
            size_t base0 = (size_t)((j0 + tj) * BSZ + b) * (3 * DM) + n * DH + 2 * DM + d4;
            size_t base1 = (size_t)((j0 + tj + 1) * BSZ + b) * (3 * DM) + n * DH + 2 * DM + d4;
            float4 v0 = *(const float4*)&g_heads[base0];
            float4 v1 = *(const float4*)&g_heads[base1];
            *(__half2*)(RVh + (d4 + 0) * H_STR + tj) = __floats2half2_rn(v0.x, v1.x);
            *(__half2*)(RVh + (d4 + 1) * H_STR + tj) = __floats2half2_rn(v0.y, v1.y);
            *(__half2*)(RVh + (d4 + 2) * H_STR + tj) = __floats2half2_rn(v0.z, v1.z);
            *(__half2*)(RVh + (d4 + 3) * H_STR + tj) = __floats2half2_rn(v0.w, v1.w);
        }

        {
            const bool diag = (jt == qt);
            float sv[16];
            const float* sp = SP  + sm_ti * F_STR + sm_cb;
            const float* bp = BDa + sm_ti * F_STR + sm_cb;
            #pragma unroll
            for (int k = 0; k < 4; k++) {
                float4 s4 = *(const float4*)(sp + 4 * k);
                float4 g4 = *(const float4*)(bp + 4 * k);
                sv[4 * k + 0] = s4.x + g4.x;
                sv[4 * k + 1] = s4.y + g4.y;
                sv[4 * k + 2] = s4.z + g4.z;
                sv[4 * k + 3] = s4.w + g4.w;
            }
            if (diag) {
                #pragma unroll
                for (int c = 0; c < 16; c++)
                    if (sm_cb + c > sm_ti) sv[c] = -INFINITY;
            }
            float rm = sv[0];
            #pragma unroll
            for (int c = 1; c < 16; c++) rm = fmaxf(rm, sv[c]);
            rm = fmaxf(rm, __shfl_xor_sync(0xffffffffu, rm, 1));
            rm = fmaxf(rm, __shfl_xor_sync(0xffffffffu, rm, 2));
            float mnew = fmaxf(mrow, rm);
            float corr = __expf(mrow - mnew);
            float rs = 0.f;
            #pragma unroll
            for (int c = 0; c < 16; c++) {
                sv[c] = __expf(sv[c] - mnew);
                rs += sv[c];
            }
            rs += __shfl_xor_sync(0xffffffffu, rs, 1);
            rs += __shfl_xor_sync(0xffffffffu, rs, 2);
            lrow = lrow * corr + rs;
            mrow = mnew;
            __half* pp = Ph + sm_ti * H_STR + sm_cb;
            #pragma unroll
            for (int k = 0; k < 8; k++)
                *(__half2*)(pp + 2 * k) = __floats2half2_rn(sv[2 * k], sv[2 * k + 1]);
            if ((l & 3) == 0) corr_s[sm_ti] = corr;
        }
        __syncthreads();

        {
            float c0 = corr_s[roff + g], c1 = corr_s[roff + g + 8];
            #pragma unroll
            for (int nt = 0; nt < 4; nt++) {
                O[nt][0] *= c0; O[nt][1] *= c0;
                O[nt][2] *= c1; O[nt][3] *= c1;
            }
        }
        #pragma unroll
        for (int ks = 0; ks < 4; ks++) {
            const int k0 = ks * 16;
            uint32_t ap[4] = {
                *(const uint32_t*)(Ph + (roff + g)     * H_STR + k0 + 2 * t),
                *(const uint32_t*)(Ph + (roff + g + 8) * H_STR + k0 + 2 * t),
                *(const uint32_t*)(Ph + (roff + g)     * H_STR + k0 + 2 * t + 8),
                *(const uint32_t*)(Ph + (roff + g + 8) * H_STR + k0 + 2 * t + 8) };
            #pragma unroll
            for (int nt = 0; nt < 4; nt++) {
                const __half* vp = RVh + (coff + nt * 8 + g) * H_STR + k0 + 2 * t;
                uint32_t bf[2] = { *(const uint32_t*)vp, *(const uint32_t*)(vp + 8) };
                MMA_F16(O[nt], ap, bf);
            }
        }

        float* tmp = BDa; BDa = BDb; BDb = tmp;
    }

    if ((l & 3) == 0) linv_s[sm_ti] = 1.f / lrow;
    __syncthreads();

    #pragma unroll
    for (int nt = 0; nt < 4; nt++) {
        const int col = n * DH + coff + nt * 8 + 2 * t;
        const int r0 = roff + g, r1 = roff + g + 8;
        const float li0 = linv_s[r0], li1 = linv_s[r1];
        size_t ro0 = (size_t)((i0 + r0) * BSZ + b) * DM;
        size_t ro1 = (size_t)((i0 + r1) * BSZ + b) * DM;
        float2 o0 = make_float2(O[nt][0] * li0, O[nt][1] * li0);
        float2 o1 = make_float2(O[nt][2] * li1, O[nt][3] * li1);
        *(float2*)&g_attnvec[ro0 + col] = o0;
        *(float2*)&g_attnvec[ro1 + col] = o1;
    }
}

// ---------------------------------------------------------------------------
// Residual add (+optional bias) + LayerNorm, one row (1024) per block.
// ---------------------------------------------------------------------------
__global__ void __launch_bounds__(256)
ln_kernel(const float* __restrict__ resid, const float* __restrict__ y,
          const float* __restrict__ bias, const float* __restrict__ gam,
          const float* __restrict__ bet, float* __restrict__ out)
{
    const int row = blockIdx.x;
    const int tid = threadIdx.x;
    __shared__ float buf[DM];
    __shared__ float red[8];

    float lsum = 0.f;
    for (int d = tid; d < DM; d += 256) {
        float v = resid[(long)row * DM + d] + y[(long)row * DM + d];
        if (bias) v += bias[d];
        buf[d] = v;
        lsum += v;
    }
    #pragma unroll
    for (int off = 16; off; off >>= 1) lsum += __shfl_xor_sync(0xffffffffu, lsum, off);
    if ((tid & 31) == 0) red[tid >> 5] = lsum;
    __syncthreads();
    float tot = 0.f;
    #pragma unroll
    for (int i = 0; i < 8; i++) tot += red[i];
    const float mean = tot * (1.f / DM);
    __syncthreads();

    float lv = 0.f;
    for (int d = tid; d < DM; d += 256) {
        float t = buf[d] - mean;
        lv += t * t;
    }
    #pragma unroll
    for (int off = 16; off; off >>= 1) lv += __shfl_xor_sync(0xffffffffu, lv, off);
    if ((tid & 31) == 0) red[tid >> 5] = lv;
    __syncthreads();
    float vtot = 0.f;
    #pragma unroll
    for (int i = 0; i < 8; i++) vtot += red[i];
    const float inv = rsqrtf(vtot * (1.f / DM) + 1e-5f);

    for (int d = tid; d < DM; d += 256)
        out[(long)row * DM + d] = (buf[d] - mean) * inv * gam[d] + bet[d];
}

// ---------------------------------------------------------------------------
// Host launch.  ncu capture slot = launch idx 3 -> lands on o-proj gemm_f16.
// ---------------------------------------------------------------------------
extern "C" void kernel_launch(void* const* d_in, const int* in_sizes, int n_in,
                              void* d_out, int out_size)
{
    const float* w      = (const float*)d_in[0];
    const float* r      = (const float*)d_in[1];
    const float* rwb    = (const float*)d_in[2];
    const float* rrb    = (const float*)d_in[3];
    // d_in[4] = attn_mask (causal triu, implicit)
    const float* qkv_w  = (const float*)d_in[5];
    const float* rnet_w = (const float*)d_in[6];
    const float* o_w    = (const float*)d_in[7];
    const float* ln1_g  = (const float*)d_in[8];
    const float* ln1_b  = (const float*)d_in[9];
    const float* ffn_w1 = (const float*)d_in[10];
    const float* ffn_b1 = (const float*)d_in[11];
    const float* ffn_w2 = (const float*)d_in[12];
    const float* ffn_b2 = (const float*)d_in[13];
    const float* ln2_g  = (const float*)d_in[14];
    const float* ln2_b  = (const float*)d_in[15];

    float *heads, *rk, *attnvec, *attnout, *x, *h, *core;
    cudaGetSymbolAddress((void**)&heads,   g_heads);
    cudaGetSymbolAddress((void**)&rk,      g_rk);
    cudaGetSymbolAddress((void**)&attnvec, g_attnvec);
    cudaGetSymbolAddress((void**)&attnout, g_attnout);
    cudaGetSymbolAddress((void**)&x,       g_x);
    cudaGetSymbolAddress((void**)&h,       g_h);
    cudaGetSymbolAddress((void**)&core,    g_core);

    // 1) qkv projection                                   (launch idx 0)
    gemm_f16<0><<<dim3(3 * DM / 128, NTOK / 128), 256>>>(w, qkv_w, heads, nullptr,
                                                         NTOK, 3 * DM, DM);
    // 2) r_k                                              (launch idx 1)
    gemm_f16<0><<<dim3(DM / 128, QL / 128), 256>>>(r, rnet_w, rk, nullptr,
                                                   QL, DM, DM);
    // 3) attention                                        (launch idx 2)
    {
        cudaFuncSetAttribute(attn_mma_kernel,
                             cudaFuncAttributeMaxDynamicSharedMemorySize, SMEM_ATT);
        attn_mma_kernel<<<dim3(QL / 64, NH, BSZ), 256, SMEM_ATT>>>(rwb, rrb);
    }
    // 4) o projection                                     (launch idx 3 = ncu slot)
    gemm_f16<0><<<dim3(DM / 128, NTOK / 128), 256>>>(attnvec, o_w, attnout, nullptr,
                                                     NTOK, DM, DM);
    // 5) x = LN(w + attn_out)
    ln_kernel<<<NTOK, 256>>>(w, attnout, nullptr, ln1_g, ln1_b, x);
    // 6) h = relu(x @ ffn_w1 + b1)
    gemm_f16<1><<<dim3(DI / 128, NTOK / 128), 256>>>(x, ffn_w1, h, ffn_b1,
                                                     NTOK, DI, DM);
    // 7) core = h @ ffn_w2
    gemm_f16<0><<<dim3(DM / 128, NTOK / 128), 256>>>(h, ffn_w2, core, nullptr,
                                                     NTOK, DM, DI);
    // 8) out = LN(x + core + b2)
    ln_kernel<<<NTOK, 256>>>(x, core, ffn_b2, ln2_g, ln2_b, (float*)d_out);
}